// round 1
// baseline (speedup 1.0000x reference)
#include <cuda_runtime.h>
#include <cuda_bf16.h>
#include <stdint.h>

// out[i] = (0 <= inputs[i] < 64) ? b[inputs[i]] : 0.0f
// Pure HBM-bound gather with a tiny (64-entry) table.

#define NUM_KEYS 64
#define TPB 256

__global__ void __launch_bounds__(TPB)
sel_xform_kernel(const int4* __restrict__ in4,
                 const float* __restrict__ b,
                 float4* __restrict__ out4,
                 int n4)
{
    __shared__ float s_b[NUM_KEYS];
    if (threadIdx.x < NUM_KEYS) s_b[threadIdx.x] = b[threadIdx.x];
    __syncthreads();

    int idx = blockIdx.x * TPB + threadIdx.x;
    int stride = gridDim.x * TPB;

    for (; idx < n4; idx += stride) {
        int4 v = in4[idx];
        float4 r;
        r.x = ((unsigned)v.x < NUM_KEYS) ? s_b[v.x] : 0.0f;
        r.y = ((unsigned)v.y < NUM_KEYS) ? s_b[v.y] : 0.0f;
        r.z = ((unsigned)v.z < NUM_KEYS) ? s_b[v.z] : 0.0f;
        r.w = ((unsigned)v.w < NUM_KEYS) ? s_b[v.w] : 0.0f;
        out4[idx] = r;
    }
}

// Tail handler for n not divisible by 4 (not needed for 33.55M, but safe).
__global__ void sel_xform_tail(const int* __restrict__ in,
                               const float* __restrict__ b,
                               float* __restrict__ out,
                               int start, int n)
{
    int i = start + blockIdx.x * blockDim.x + threadIdx.x;
    if (i < n) {
        int v = in[i];
        out[i] = ((unsigned)v < NUM_KEYS) ? b[v] : 0.0f;
    }
}

extern "C" void kernel_launch(void* const* d_in, const int* in_sizes, int n_in,
                              void* d_out, int out_size)
{
    const int*   inputs = (const int*)d_in[0];
    const float* b      = (const float*)d_in[1];
    // d_in[2] = keys (arange(64)) — identity mapping, unused.

    int n  = in_sizes[0];
    int n4 = n >> 2;

    int blocks = (n4 + TPB - 1) / TPB;
    if (blocks > 0) {
        sel_xform_kernel<<<blocks, TPB>>>((const int4*)inputs, b,
                                          (float4*)d_out, n4);
    }

    int tail_start = n4 << 2;
    if (tail_start < n) {
        int tail = n - tail_start;
        sel_xform_tail<<<(tail + 255) / 256, 256>>>(inputs, b,
                                                    (float*)d_out, tail_start, n);
    }
}

// round 3
// speedup vs baseline: 1.0192x; 1.0192x over previous
#include <cuda_runtime.h>
#include <cuda_bf16.h>
#include <stdint.h>

// out[i] = (0 <= inputs[i] < 64) ? b[inputs[i]] : 0.0f
// Pure streaming HBM-bound gather, 64-entry table in shared memory.
// V2: 4x int4 per thread (front-batched -> MLP=4), streaming cache hints.

#define NUM_KEYS 64
#define TPB 256
#define VEC 4   // int4 loads per thread

__device__ __forceinline__ float4 lut4(int4 v, const float* __restrict__ s_b)
{
    float4 r;
    r.x = ((unsigned)v.x < NUM_KEYS) ? s_b[v.x] : 0.0f;
    r.y = ((unsigned)v.y < NUM_KEYS) ? s_b[v.y] : 0.0f;
    r.z = ((unsigned)v.z < NUM_KEYS) ? s_b[v.z] : 0.0f;
    r.w = ((unsigned)v.w < NUM_KEYS) ? s_b[v.w] : 0.0f;
    return r;
}

__global__ void __launch_bounds__(TPB)
sel_xform_kernel(const int4* __restrict__ in4,
                 const float* __restrict__ b,
                 float4* __restrict__ out4,
                 int n4)
{
    __shared__ float s_b[NUM_KEYS];
    if (threadIdx.x < NUM_KEYS) s_b[threadIdx.x] = b[threadIdx.x];
    __syncthreads();

    // Block-local batching: thread t handles base + t + k*TPB, k=0..VEC-1.
    int base = blockIdx.x * (TPB * VEC) + threadIdx.x;

    if (base + (VEC - 1) * TPB < n4) {
        // Fast path: front-batch all VEC loads (independent -> MLP=VEC).
        int4 v[VEC];
        #pragma unroll
        for (int k = 0; k < VEC; k++)
            v[k] = __ldcs(&in4[base + k * TPB]);
        #pragma unroll
        for (int k = 0; k < VEC; k++) {
            float4 r = lut4(v[k], s_b);
            __stcs(&out4[base + k * TPB], r);
        }
    } else {
        #pragma unroll
        for (int k = 0; k < VEC; k++) {
            int idx = base + k * TPB;
            if (idx < n4) {
                float4 r = lut4(__ldcs(&in4[idx]), s_b);
                __stcs(&out4[idx], r);
            }
        }
    }
}

// Tail handler for n not divisible by 4 (not needed for 33.55M, but safe).
__global__ void sel_xform_tail(const int* __restrict__ in,
                               const float* __restrict__ b,
                               float* __restrict__ out,
                               int start, int n)
{
    int i = start + blockIdx.x * blockDim.x + threadIdx.x;
    if (i < n) {
        int v = in[i];
        out[i] = ((unsigned)v < NUM_KEYS) ? b[v] : 0.0f;
    }
}

extern "C" void kernel_launch(void* const* d_in, const int* in_sizes, int n_in,
                              void* d_out, int out_size)
{
    const int*   inputs = (const int*)d_in[0];
    const float* b      = (const float*)d_in[1];
    // d_in[2] = keys (arange(64)) — identity mapping, unused.

    int n  = in_sizes[0];
    int n4 = n >> 2;

    int per_block = TPB * VEC;
    int blocks = (n4 + per_block - 1) / per_block;
    if (blocks > 0) {
        sel_xform_kernel<<<blocks, TPB>>>((const int4*)inputs, b,
                                          (float4*)d_out, n4);
    }

    int tail_start = n4 << 2;
    if (tail_start < n) {
        int tail = n - tail_start;
        sel_xform_tail<<<(tail + 255) / 256, 256>>>(inputs, b,
                                                    (float*)d_out, tail_start, n);
    }
}

// round 6
// speedup vs baseline: 1.0243x; 1.0050x over previous
#include <cuda_runtime.h>
#include <cuda_bf16.h>
#include <stdint.h>

// out[i] = (0 <= inputs[i] < 64) ? b[inputs[i]] : 0.0f
// Pure streaming HBM-bound gather, 64-entry table in shared memory.
// V3: 8x int4 per thread (front-batched -> MLP=8), streaming cache hints.

#define NUM_KEYS 64
#define TPB 256
#define VEC 8   // int4 loads per thread

__device__ __forceinline__ float4 lut4(int4 v, const float* __restrict__ s_b)
{
    float4 r;
    r.x = ((unsigned)v.x < NUM_KEYS) ? s_b[v.x] : 0.0f;
    r.y = ((unsigned)v.y < NUM_KEYS) ? s_b[v.y] : 0.0f;
    r.z = ((unsigned)v.z < NUM_KEYS) ? s_b[v.z] : 0.0f;
    r.w = ((unsigned)v.w < NUM_KEYS) ? s_b[v.w] : 0.0f;
    return r;
}

__global__ void __launch_bounds__(TPB)
sel_xform_kernel(const int4* __restrict__ in4,
                 const float* __restrict__ b,
                 float4* __restrict__ out4,
                 int n4)
{
    __shared__ float s_b[NUM_KEYS];
    if (threadIdx.x < NUM_KEYS) s_b[threadIdx.x] = b[threadIdx.x];
    __syncthreads();

    // Block-local batching: thread t handles base + t + k*TPB, k=0..VEC-1.
    int base = blockIdx.x * (TPB * VEC) + threadIdx.x;

    if (base + (VEC - 1) * TPB < n4) {
        // Fast path: front-batch all VEC loads (independent -> MLP=VEC).
        int4 v[VEC];
        #pragma unroll
        for (int k = 0; k < VEC; k++)
            v[k] = __ldcs(&in4[base + k * TPB]);
        #pragma unroll
        for (int k = 0; k < VEC; k++) {
            float4 r = lut4(v[k], s_b);
            __stcs(&out4[base + k * TPB], r);
        }
    } else {
        #pragma unroll
        for (int k = 0; k < VEC; k++) {
            int idx = base + k * TPB;
            if (idx < n4) {
                float4 r = lut4(__ldcs(&in4[idx]), s_b);
                __stcs(&out4[idx], r);
            }
        }
    }
}

// Tail handler for n not divisible by 4 (not needed for 33.55M, but safe).
__global__ void sel_xform_tail(const int* __restrict__ in,
                               const float* __restrict__ b,
                               float* __restrict__ out,
                               int start, int n)
{
    int i = start + blockIdx.x * blockDim.x + threadIdx.x;
    if (i < n) {
        int v = in[i];
        out[i] = ((unsigned)v < NUM_KEYS) ? b[v] : 0.0f;
    }
}

extern "C" void kernel_launch(void* const* d_in, const int* in_sizes, int n_in,
                              void* d_out, int out_size)
{
    const int*   inputs = (const int*)d_in[0];
    const float* b      = (const float*)d_in[1];
    // d_in[2] = keys (arange(64)) — identity mapping, unused.

    int n  = in_sizes[0];
    int n4 = n >> 2;

    int per_block = TPB * VEC;
    int blocks = (n4 + per_block - 1) / per_block;
    if (blocks > 0) {
        sel_xform_kernel<<<blocks, TPB>>>((const int4*)inputs, b,
                                          (float4*)d_out, n4);
    }

    int tail_start = n4 << 2;
    if (tail_start < n) {
        int tail = n - tail_start;
        sel_xform_tail<<<(tail + 255) / 256, 256>>>(inputs, b,
                                                    (float*)d_out, tail_start, n);
    }
}